// round 7
// baseline (speedup 1.0000x reference)
#include <cuda_runtime.h>
#include <cuda_fp16.h>
#include <cstdint>

// ================= config =================
#define THREADS 256
#define TILE_M 128
#define KDIM 128
#define NDIM 128
#define M_TOTAL 16
#define NPATH 4

// W converted to fp16, transposed to [p][n][k] (k contiguous) — 128KB, L2-resident.
__device__ __half g_wt[NPATH * NDIM * KDIM];

// ================= helpers =================

__device__ __forceinline__ uint32_t smem_u32(const void* p) {
    uint32_t a;
    asm("{ .reg .u64 t; cvta.to.shared.u64 t, %1; cvt.u32.u64 %0, t; }"
        : "=r"(a) : "l"(p));
    return a;
}

#define LDMATRIX_X4(R0, R1, R2, R3, ADDR)                                  \
    asm volatile("ldmatrix.sync.aligned.m8n8.x4.shared.b16 {%0,%1,%2,%3}, [%4];" \
        : "=r"(R0), "=r"(R1), "=r"(R2), "=r"(R3) : "r"(ADDR))

#define MMA16816(D, A, B0, B1)                                             \
    asm volatile("mma.sync.aligned.m16n8k16.row.col.f32.f16.f16.f32 "      \
        "{%0,%1,%2,%3}, {%4,%5,%6,%7}, {%8,%9}, {%0,%1,%2,%3};"            \
        : "+f"((D)[0]), "+f"((D)[1]), "+f"((D)[2]), "+f"((D)[3])           \
        : "r"((A)[0]), "r"((A)[1]), "r"((A)[2]), "r"((A)[3]),              \
          "r"(B0), "r"(B1))

// ================= prep kernel: W fp32 [p][k][n] -> fp16 [p][n][k] =================

__global__ void prep_w_kernel(const float* __restrict__ w) {
    int idx = blockIdx.x * blockDim.x + threadIdx.x;   // 65536 total
    int p = idx >> 14;
    int n = (idx >> 7) & 127;
    int k = idx & 127;
    g_wt[idx] = __float2half_rn(w[(p << 14) + (k << 7) + n]);
}

// ================= main kernel =================
// smem: [0, 32KB)  A tile fp16, row-major [row][k], XOR-swizzled 16B chunks
//       [32KB,64KB) B tile fp16, row-major [n][k], same swizzle
// swizzle: phys_off(row, chunk16B) = row*256 + ((chunk ^ (row & 7)) << 4)

__global__ void __launch_bounds__(THREADS, 2)
irreps_mma_kernel(const float* __restrict__ x,
                  const int* __restrict__ seg,
                  float* __restrict__ out,
                  int n_nodes) {
    extern __shared__ char smem[];
    char* As = smem;
    char* Bs = smem + 32768;

    const int tid = threadIdx.x;
    const int lane = tid & 31;
    const int wid = tid >> 5;
    const int tile = blockIdx.x;
    const int m = blockIdx.y;
    const int node0 = tile * TILE_M;
    const int p = seg[m];

    // ---- load B tile: g_wt[p][n][k] -> Bs (swizzled), 2048 x 16B chunks ----
    const __half* wt = g_wt + (p << 14);
    #pragma unroll
    for (int i = 0; i < 8; ++i) {
        int cidx = i * THREADS + tid;       // chunk index
        int row = cidx >> 4;                // n
        int ch  = cidx & 15;                // k-chunk (8 halves)
        uint4 v = *reinterpret_cast<const uint4*>(wt + (row << 7) + (ch << 3));
        uint32_t off = (uint32_t)(row << 8) + (uint32_t)(((ch ^ (row & 7)) << 4));
        *reinterpret_cast<uint4*>(Bs + off) = v;
    }

    // ---- load A tile: x fp32 -> fp16 -> As (swizzled) ----
    #pragma unroll
    for (int i = 0; i < 8; ++i) {
        int cidx = i * THREADS + tid;
        int row = cidx >> 4;                // node within tile
        int ch  = cidx & 15;
        int node = node0 + row;
        uint4 hv = make_uint4(0u, 0u, 0u, 0u);
        if (node < n_nodes) {
            const float4* g = reinterpret_cast<const float4*>(
                x + (((size_t)node * M_TOTAL + m) << 7) + (ch << 3));
            float4 a = g[0];
            float4 b = g[1];
            __half2 h0 = __floats2half2_rn(a.x, a.y);
            __half2 h1 = __floats2half2_rn(a.z, a.w);
            __half2 h2 = __floats2half2_rn(b.x, b.y);
            __half2 h3 = __floats2half2_rn(b.z, b.w);
            hv.x = *reinterpret_cast<uint32_t*>(&h0);
            hv.y = *reinterpret_cast<uint32_t*>(&h1);
            hv.z = *reinterpret_cast<uint32_t*>(&h2);
            hv.w = *reinterpret_cast<uint32_t*>(&h3);
        }
        uint32_t off = (uint32_t)(row << 8) + (uint32_t)(((ch ^ (row & 7)) << 4));
        *reinterpret_cast<uint4*>(As + off) = hv;
    }
    __syncthreads();

    // ---- MMA: warp (wid&3 -> 32-row group, wid>>2 -> 64-col group) ----
    const int wr = (wid & 3) * 32;
    const int wc = (wid >> 2) * 64;
    const uint32_t sA = smem_u32(As);
    const uint32_t sB = smem_u32(Bs);

    // A ldmatrix lane addressing: rows wr + mt*16 + (lane&15), chunk 2*ks + (lane>>4)
    const int a_row = wr + (lane & 15);
    const uint32_t a_base0 = sA + (uint32_t)(a_row << 8);
    const uint32_t a_base1 = sA + (uint32_t)((a_row + 16) << 8);
    const int a_sw = a_row & 7;                 // same for row and row+16
    const int a_hi = lane >> 4;                 // 0/1

    // B ldmatrix lane addressing: n = wc + nt4*16 + (lane&7) + ((lane>>4)<<3),
    // chunk 2*ks + ((lane>>3)&1)
    const int b_row = wc + (lane & 7) + ((lane >> 4) << 3);
    const uint32_t b_base = sB + (uint32_t)(b_row << 8);
    const int b_sw = b_row & 7;
    const int b_hi = (lane >> 3) & 1;

    float acc[2][8][4];
    #pragma unroll
    for (int mt = 0; mt < 2; ++mt)
        #pragma unroll
        for (int nt = 0; nt < 8; ++nt)
            #pragma unroll
            for (int q = 0; q < 4; ++q)
                acc[mt][nt][q] = 0.0f;

    #pragma unroll
    for (int ks = 0; ks < 8; ++ks) {
        const int ach = (2 * ks + a_hi) ^ a_sw;
        const int bch = (2 * ks + b_hi) ^ b_sw;

        uint32_t a[2][4];
        LDMATRIX_X4(a[0][0], a[0][1], a[0][2], a[0][3], a_base0 + (ach << 4));
        LDMATRIX_X4(a[1][0], a[1][1], a[1][2], a[1][3], a_base1 + (ach << 4));

        uint32_t b[4][4];   // b[nt4] = {b0(n0), b1(n0), b0(n0+8), b1(n0+8)}
        #pragma unroll
        for (int nt4 = 0; nt4 < 4; ++nt4) {
            LDMATRIX_X4(b[nt4][0], b[nt4][1], b[nt4][2], b[nt4][3],
                        b_base + (uint32_t)(nt4 << 12) + (bch << 4));
        }

        #pragma unroll
        for (int mt = 0; mt < 2; ++mt) {
            #pragma unroll
            for (int nt = 0; nt < 8; ++nt) {
                MMA16816(acc[mt][nt], a[mt],
                         b[nt >> 1][(nt & 1) * 2], b[nt >> 1][(nt & 1) * 2 + 1]);
            }
        }
    }

    // ---- epilogue: direct STG.64 (full 32B sectors per 4-lane group) ----
    const int row_in = lane >> 2;
    const int col_in = (lane & 3) << 1;
    #pragma unroll
    for (int mt = 0; mt < 2; ++mt) {
        #pragma unroll
        for (int q2 = 0; q2 < 2; ++q2) {
            int r = wr + mt * 16 + q2 * 8 + row_in;
            int node = node0 + r;
            if (node < n_nodes) {
                float* op = out + (((size_t)node * M_TOTAL + m) << 7) + wc + col_in;
                #pragma unroll
                for (int nt = 0; nt < 8; ++nt) {
                    float2 v;
                    v.x = acc[mt][nt][q2 * 2];
                    v.y = acc[mt][nt][q2 * 2 + 1];
                    *reinterpret_cast<float2*>(op + nt * 8) = v;
                }
            }
        }
    }
}

// ================= launch =================

extern "C" void kernel_launch(void* const* d_in, const int* in_sizes, int n_in,
                              void* d_out, int out_size) {
    const float* x   = (const float*)d_in[0];
    const float* w   = (const float*)d_in[1];
    const int*   seg = (const int*)d_in[2];
    float* out = (float*)d_out;

    int n_nodes = in_sizes[0] / (M_TOTAL * KDIM);     // 50000
    int ntiles = (n_nodes + TILE_M - 1) / TILE_M;     // 391

    // prep: W -> fp16 transposed [p][n][k]
    prep_w_kernel<<<(NPATH * NDIM * KDIM) / 256, 256>>>(w);

    static bool attr_set = false;
    if (!attr_set) {
        cudaFuncSetAttribute(irreps_mma_kernel,
                             cudaFuncAttributeMaxDynamicSharedMemorySize, 65536);
        attr_set = true;
    }

    dim3 grid(ntiles, M_TOTAL);
    irreps_mma_kernel<<<grid, THREADS, 65536>>>(x, seg, out, n_nodes);
}

// round 8
// speedup vs baseline: 1.0372x; 1.0372x over previous
#include <cuda_runtime.h>
#include <cuda_fp16.h>
#include <cstdint>

// ================= config =================
#define THREADS 256
#define SLICES 9          // 9 * 16 = 144 persistent CTAs (one wave, 1 CTA/SM)
#define TILE_M 128
#define KDIM 128
#define NDIM 128
#define M_TOTAL 16
#define NPATH 4

// W converted to fp16, transposed to [p][n][k] (k contiguous) — 128KB, L2-resident.
__device__ __half g_wt[NPATH * NDIM * KDIM];

// ================= helpers =================

__device__ __forceinline__ uint32_t smem_u32(const void* p) {
    uint32_t a;
    asm("{ .reg .u64 t; cvta.to.shared.u64 t, %1; cvt.u32.u64 %0, t; }"
        : "=r"(a) : "l"(p));
    return a;
}

#define LDMATRIX_X4(R0, R1, R2, R3, ADDR)                                  \
    asm volatile("ldmatrix.sync.aligned.m8n8.x4.shared.b16 {%0,%1,%2,%3}, [%4];" \
        : "=r"(R0), "=r"(R1), "=r"(R2), "=r"(R3) : "r"(ADDR))

#define MMA16816(D, A, B0, B1)                                             \
    asm volatile("mma.sync.aligned.m16n8k16.row.col.f32.f16.f16.f32 "      \
        "{%0,%1,%2,%3}, {%4,%5,%6,%7}, {%8,%9}, {%0,%1,%2,%3};"            \
        : "+f"((D)[0]), "+f"((D)[1]), "+f"((D)[2]), "+f"((D)[3])           \
        : "r"((A)[0]), "r"((A)[1]), "r"((A)[2]), "r"((A)[3]),              \
          "r"(B0), "r"(B1))

#define STS64(ADDR, LO, HI)                                                \
    asm volatile("st.shared.v2.b32 [%0], {%1,%2};"                          \
        :: "r"(ADDR), "r"(LO), "r"(HI) : "memory")

// ================= prep kernel: W fp32 [p][k][n] -> fp16 [p][n][k] =================

__global__ void prep_w_kernel(const float* __restrict__ w) {
    int idx = blockIdx.x * blockDim.x + threadIdx.x;   // 65536 total
    int p = idx >> 14;
    int n = (idx >> 7) & 127;
    int k = idx & 127;
    g_wt[idx] = __float2half_rn(w[(p << 14) + (k << 7) + n]);
}

// ================= main kernel =================
// smem: two 32KB A-tile buffers (fp16, row-major [row][k], XOR-swizzled 16B chunks)
// swizzle: phys(row, ch16) = row*256 + ((ch ^ (row&7)) << 4)
// B[p] (fp16 [n][k]) staged once through buf1, then lives in registers per warp.

__global__ void __launch_bounds__(THREADS, 1)
irreps_pers_kernel(const float* __restrict__ x,
                   const int* __restrict__ seg,
                   float* __restrict__ out,
                   int n_nodes, int ntiles) {
    extern __shared__ char smem[];
    char* A0 = smem;
    char* A1 = smem + 32768;

    const int tid = threadIdx.x;
    const int lane = tid & 31;
    const int wid = tid >> 5;
    const int m = blockIdx.y;
    const int s = blockIdx.x;
    const int p = seg[m];

    // warp tile: 64 rows x 32 cols; 2 row-groups x 4 col-groups
    const int wr = (wid >> 2) * 64;
    const int wc = (wid & 3) * 32;

    const uint32_t sA0 = smem_u32(A0);
    const uint32_t sA1 = smem_u32(A1);

    // ---- stage B[p] into buf1 (swizzled), then LDSM into registers ----
    {
        const __half* wt = g_wt + (p << 14);
        #pragma unroll
        for (int i = 0; i < 8; ++i) {
            int cidx = i * THREADS + tid;
            int row = cidx >> 4;           // n
            int ch  = cidx & 15;           // 16B k-chunk
            uint4 v = *reinterpret_cast<const uint4*>(wt + (row << 7) + (ch << 3));
            uint32_t off = (uint32_t)(row << 8) + (uint32_t)(((ch ^ (row & 7)) << 4));
            *reinterpret_cast<uint4*>(A1 + off) = v;
        }
    }
    __syncthreads();

    // B fragments: breg[ks][nt4][4]; nt4 covers 16 cols (two n8 fragments)
    const int b_row = wc + (lane & 7) + ((lane >> 4) << 3);
    const uint32_t b_base = sA1 + (uint32_t)(b_row << 8);
    const int b_sw = b_row & 7;
    const int b_hi = (lane >> 3) & 1;

    uint32_t breg[8][2][4];
    #pragma unroll
    for (int ks = 0; ks < 8; ++ks) {
        const int bch = (2 * ks + b_hi) ^ b_sw;
        #pragma unroll
        for (int nt4 = 0; nt4 < 2; ++nt4) {
            LDMATRIX_X4(breg[ks][nt4][0], breg[ks][nt4][1],
                        breg[ks][nt4][2], breg[ks][nt4][3],
                        b_base + (uint32_t)(nt4 << 12) + (uint32_t)(bch << 4));
        }
    }
    __syncthreads();   // all warps done reading B before buf1 is reused for A

    // ---- A fragment addressing (constant per thread) ----
    const int a_hi = lane >> 4;
    const int a_sw = lane & 7;          // (wr + mt*16 + (lane&15)) & 7 == lane & 7
    uint32_t aoff[4];
    #pragma unroll
    for (int mt = 0; mt < 4; ++mt)
        aoff[mt] = (uint32_t)((wr + mt * 16 + (lane & 15)) << 8);

    // ---- A staging constants: fc = tid&31 (float4 col), rsub = tid>>5 ----
    const int fc = tid & 31;
    const int rsub = tid >> 5;
    const uint32_t swz = (uint32_t)((((fc >> 1) ^ rsub) << 4) | ((fc & 1) << 3));

    const int cnt = (ntiles - s + SLICES - 1) / SLICES;   // >= 43 for all s<9

    // ---- preload tile 0 into buf0 ----
    {
        const int nb = s * TILE_M;
        #pragma unroll
        for (int u = 0; u < 16; ++u) {
            int row = u * 8 + rsub;
            int node = nb + row;
            float4 v = make_float4(0.f, 0.f, 0.f, 0.f);
            if (node < n_nodes)
                v = reinterpret_cast<const float4*>(
                        x + (((size_t)node * M_TOTAL + m) << 7))[fc];
            __half2 h0 = __floats2half2_rn(v.x, v.y);
            __half2 h1 = __floats2half2_rn(v.z, v.w);
            STS64(sA0 + (uint32_t)(row << 8) + swz,
                  *reinterpret_cast<uint32_t*>(&h0),
                  *reinterpret_cast<uint32_t*>(&h1));
        }
    }
    __syncthreads();

    float4 stg[8];

    for (int i = 0; i < cnt; ++i) {
        const int j = i & 1;
        const int t = s + i * SLICES;
        const bool nx = (i + 1 < cnt);
        const int nb_next = (s + (i + 1) * SLICES) * TILE_M;
        const uint32_t sA = j ? sA1 : sA0;
        const uint32_t sAn = j ? sA0 : sA1;

        float acc[4][4][4];
        #pragma unroll
        for (int mt = 0; mt < 4; ++mt)
            #pragma unroll
            for (int nt = 0; nt < 4; ++nt)
                #pragma unroll
                for (int q = 0; q < 4; ++q)
                    acc[mt][nt][q] = 0.0f;

        // ---- issue LDGs for next tile, first half (rows 0..63) ----
        if (nx) {
            #pragma unroll
            for (int u = 0; u < 8; ++u) {
                int node = nb_next + u * 8 + rsub;
                stg[u] = make_float4(0.f, 0.f, 0.f, 0.f);
                if (node < n_nodes)
                    stg[u] = reinterpret_cast<const float4*>(
                                x + (((size_t)node * M_TOTAL + m) << 7))[fc];
            }
        }

        // ---- mma ks 0..3 ----
        #pragma unroll
        for (int ks = 0; ks < 4; ++ks) {
            const int ach = (2 * ks + a_hi) ^ a_sw;
            uint32_t a[4][4];
            #pragma unroll
            for (int mt = 0; mt < 4; ++mt)
                LDMATRIX_X4(a[mt][0], a[mt][1], a[mt][2], a[mt][3],
                            sA + aoff[mt] + (uint32_t)(ach << 4));
            #pragma unroll
            for (int mt = 0; mt < 4; ++mt)
                #pragma unroll
                for (int nt = 0; nt < 4; ++nt)
                    MMA16816(acc[mt][nt], a[mt],
                             breg[ks][nt >> 1][(nt & 1) * 2],
                             breg[ks][nt >> 1][(nt & 1) * 2 + 1]);
        }

        // ---- convert+store half0, issue LDGs half1 ----
        if (nx) {
            #pragma unroll
            for (int u = 0; u < 8; ++u) {
                __half2 h0 = __floats2half2_rn(stg[u].x, stg[u].y);
                __half2 h1 = __floats2half2_rn(stg[u].z, stg[u].w);
                STS64(sAn + (uint32_t)((u * 8 + rsub) << 8) + swz,
                      *reinterpret_cast<uint32_t*>(&h0),
                      *reinterpret_cast<uint32_t*>(&h1));
            }
            #pragma unroll
            for (int u = 0; u < 8; ++u) {
                int node = nb_next + 64 + u * 8 + rsub;
                stg[u] = make_float4(0.f, 0.f, 0.f, 0.f);
                if (node < n_nodes)
                    stg[u] = reinterpret_cast<const float4*>(
                                x + (((size_t)node * M_TOTAL + m) << 7))[fc];
            }
        }

        // ---- mma ks 4..7 ----
        #pragma unroll
        for (int ks = 4; ks < 8; ++ks) {
            const int ach = (2 * ks + a_hi) ^ a_sw;
            uint32_t a[4][4];
            #pragma unroll
            for (int mt = 0; mt < 4; ++mt)
                LDMATRIX_X4(a[mt][0], a[mt][1], a[mt][2], a[mt][3],
                            sA + aoff[mt] + (uint32_t)(ach << 4));
            #pragma unroll
            for (int mt = 0; mt < 4; ++mt)
                #pragma unroll
                for (int nt = 0; nt < 4; ++nt)
                    MMA16816(acc[mt][nt], a[mt],
                             breg[ks][nt >> 1][(nt & 1) * 2],
                             breg[ks][nt >> 1][(nt & 1) * 2 + 1]);
        }

        // ---- convert+store half1 ----
        if (nx) {
            #pragma unroll
            for (int u = 0; u < 8; ++u) {
                __half2 h0 = __floats2half2_rn(stg[u].x, stg[u].y);
                __half2 h1 = __floats2half2_rn(stg[u].z, stg[u].w);
                STS64(sAn + (uint32_t)((64 + u * 8 + rsub) << 8) + swz,
                      *reinterpret_cast<uint32_t*>(&h0),
                      *reinterpret_cast<uint32_t*>(&h1));
            }
        }

        // ---- epilogue: store tile t ----
        {
            const int node0 = t * TILE_M;
            const int row_in = lane >> 2;
            const int col_in = (lane & 3) << 1;
            #pragma unroll
            for (int mt = 0; mt < 4; ++mt) {
                #pragma unroll
                for (int q2 = 0; q2 < 2; ++q2) {
                    int node = node0 + wr + mt * 16 + q2 * 8 + row_in;
                    if (node < n_nodes) {
                        float* op = out + (((size_t)node * M_TOTAL + m) << 7)
                                  + wc + col_in;
                        #pragma unroll
                        for (int nt = 0; nt < 4; ++nt) {
                            float2 v;
                            v.x = acc[mt][nt][q2 * 2];
                            v.y = acc[mt][nt][q2 * 2 + 1];
                            *reinterpret_cast<float2*>(op + nt * 8) = v;
                        }
                    }
                }
            }
        }
        __syncthreads();
    }
}

// ================= launch =================

extern "C" void kernel_launch(void* const* d_in, const int* in_sizes, int n_in,
                              void* d_out, int out_size) {
    const float* x   = (const float*)d_in[0];
    const float* w   = (const float*)d_in[1];
    const int*   seg = (const int*)d_in[2];
    float* out = (float*)d_out;

    int n_nodes = in_sizes[0] / (M_TOTAL * KDIM);     // 50000
    int ntiles = (n_nodes + TILE_M - 1) / TILE_M;     // 391

    prep_w_kernel<<<(NPATH * NDIM * KDIM) / 256, 256>>>(w);

    static bool attr_set = false;
    if (!attr_set) {
        cudaFuncSetAttribute(irreps_pers_kernel,
                             cudaFuncAttributeMaxDynamicSharedMemorySize, 65536);
        attr_set = true;
    }

    dim3 grid(SLICES, M_TOTAL);   // 9 x 16 = 144 persistent CTAs
    irreps_pers_kernel<<<grid, THREADS, 65536>>>(x, seg, out, n_nodes, ntiles);
}

// round 9
// speedup vs baseline: 1.0880x; 1.0490x over previous
#include <cuda_runtime.h>
#include <cuda_fp16.h>
#include <cstdint>

// ================= config =================
#define THREADS 512
#define SLICES 9          // 9 * 16 = 144 persistent CTAs (one wave, 1 CTA/SM)
#define TILE_M 128
#define KDIM 128
#define NDIM 128
#define M_TOTAL 16
#define NPATH 4

// W converted to fp16, transposed to [p][n][k] (k contiguous) — 128KB, L2-resident.
__device__ __half g_wt[NPATH * NDIM * KDIM];

// ================= helpers =================

__device__ __forceinline__ uint32_t smem_u32(const void* p) {
    uint32_t a;
    asm("{ .reg .u64 t; cvta.to.shared.u64 t, %1; cvt.u32.u64 %0, t; }"
        : "=r"(a) : "l"(p));
    return a;
}

#define LDMATRIX_X4(R0, R1, R2, R3, ADDR)                                  \
    asm volatile("ldmatrix.sync.aligned.m8n8.x4.shared.b16 {%0,%1,%2,%3}, [%4];" \
        : "=r"(R0), "=r"(R1), "=r"(R2), "=r"(R3) : "r"(ADDR))

#define MMA16816(D, A, B0, B1)                                             \
    asm volatile("mma.sync.aligned.m16n8k16.row.col.f32.f16.f16.f32 "      \
        "{%0,%1,%2,%3}, {%4,%5,%6,%7}, {%8,%9}, {%0,%1,%2,%3};"            \
        : "+f"((D)[0]), "+f"((D)[1]), "+f"((D)[2]), "+f"((D)[3])           \
        : "r"((A)[0]), "r"((A)[1]), "r"((A)[2]), "r"((A)[3]),              \
          "r"(B0), "r"(B1))

#define STS64(ADDR, LO, HI)                                                \
    asm volatile("st.shared.v2.b32 [%0], {%1,%2};"                          \
        :: "r"(ADDR), "r"(LO), "r"(HI) : "memory")

// ================= prep kernel: W fp32 [p][k][n] -> fp16 [p][n][k] =================

__global__ void prep_w_kernel(const float* __restrict__ w) {
    int idx = blockIdx.x * blockDim.x + threadIdx.x;   // 65536 total
    int p = idx >> 14;
    int n = (idx >> 7) & 127;
    int k = idx & 127;
    g_wt[idx] = __float2half_rn(w[(p << 14) + (k << 7) + n]);
}

// ================= main kernel =================
// 512 threads = 16 warps, warp grid 2(Mrow-groups of 64) x 8(Ncol-groups of 16).
// smem: two 32KB A-tile buffers (fp16, row-major [row][k], XOR-swizzled 16B chunks)
// swizzle: phys(row, ch16) = row*256 + ((ch ^ (row&7)) << 4)
// B[p] (fp16 [n][k]) staged once through buf1, then lives in registers (32/thread).

__global__ void __launch_bounds__(THREADS, 1)
irreps_pers_kernel(const float* __restrict__ x,
                   const int* __restrict__ seg,
                   float* __restrict__ out,
                   int n_nodes, int ntiles) {
    extern __shared__ char smem[];
    char* A1 = smem + 32768;

    const int tid = threadIdx.x;
    const int lane = tid & 31;
    const int wid = tid >> 5;
    const int m = blockIdx.y;
    const int s = blockIdx.x;
    const int p = seg[m];

    // warp tile: 64 rows x 16 cols
    const int wr = (wid >> 3) * 64;
    const int wc = (wid & 7) * 16;

    const uint32_t sA0 = smem_u32(smem);
    const uint32_t sA1 = sA0 + 32768u;

    // ---- stage B[p] into buf1 (swizzled) ----
    {
        const __half* wt = g_wt + (p << 14);
        #pragma unroll
        for (int i = 0; i < 4; ++i) {
            int cidx = i * THREADS + tid;      // 2048 16B chunks
            int row = cidx >> 4;               // n
            int ch  = cidx & 15;               // 16B k-chunk
            uint4 v = *reinterpret_cast<const uint4*>(wt + (row << 7) + (ch << 3));
            uint32_t off = (uint32_t)(row << 8) + (uint32_t)(((ch ^ (row & 7)) << 4));
            *reinterpret_cast<uint4*>(A1 + off) = v;
        }
    }
    __syncthreads();

    // ---- B fragments in registers: breg[ks][4] covers this warp's 16 cols ----
    const int b_row = wc + (lane & 7) + ((lane >> 4) << 3);
    const uint32_t b_base = sA1 + (uint32_t)(b_row << 8);
    const int b_sw = b_row & 7;
    const int b_hi = (lane >> 3) & 1;

    uint32_t breg[8][4];
    #pragma unroll
    for (int ks = 0; ks < 8; ++ks) {
        const int bch = (2 * ks + b_hi) ^ b_sw;
        LDMATRIX_X4(breg[ks][0], breg[ks][1], breg[ks][2], breg[ks][3],
                    b_base + (uint32_t)(bch << 4));
    }
    __syncthreads();   // all warps done reading B before buf1 is reused for A

    // ---- A fragment addressing (constant per thread) ----
    const int a_hi = lane >> 4;
    const int a_sw = lane & 7;
    uint32_t aoff[4];
    #pragma unroll
    for (int mt = 0; mt < 4; ++mt)
        aoff[mt] = (uint32_t)((wr + mt * 16 + (lane & 15)) << 8);

    // ---- A staging constants ----
    const int fc = tid & 31;                 // float4 column 0..31
    const int rsub = tid >> 5;               // 0..15
    const uint32_t swz = (uint32_t)((((fc >> 1) ^ (rsub & 7)) << 4) | ((fc & 1) << 3));

    const int cnt = (ntiles - s + SLICES - 1) / SLICES;

    // ---- preload tile 0 into buf0 (rows u*16 + rsub) ----
    {
        const int nb = s * TILE_M;
        #pragma unroll
        for (int u = 0; u < 8; ++u) {
            int row = u * 16 + rsub;
            int node = nb + row;
            float4 v = make_float4(0.f, 0.f, 0.f, 0.f);
            if (node < n_nodes)
                v = reinterpret_cast<const float4*>(
                        x + (((size_t)node * M_TOTAL + m) << 7))[fc];
            __half2 h0 = __floats2half2_rn(v.x, v.y);
            __half2 h1 = __floats2half2_rn(v.z, v.w);
            STS64(sA0 + (uint32_t)(row << 8) + swz,
                  *reinterpret_cast<uint32_t*>(&h0),
                  *reinterpret_cast<uint32_t*>(&h1));
        }
    }
    __syncthreads();

    float4 stg[4];

    for (int i = 0; i < cnt; ++i) {
        const int j = i & 1;
        const int t = s + i * SLICES;
        const bool nx = (i + 1 < cnt);
        const int nb_next = (s + (i + 1) * SLICES) * TILE_M;
        const uint32_t sA = j ? sA1 : sA0;
        const uint32_t sAn = j ? sA0 : sA1;

        float acc[4][2][4];
        #pragma unroll
        for (int mt = 0; mt < 4; ++mt)
            #pragma unroll
            for (int nt = 0; nt < 2; ++nt)
                #pragma unroll
                for (int q = 0; q < 4; ++q)
                    acc[mt][nt][q] = 0.0f;

        // ---- issue LDGs for next tile, half0 (rows 0..63: u*16+rsub, u<4) ----
        if (nx) {
            #pragma unroll
            for (int u = 0; u < 4; ++u) {
                int node = nb_next + u * 16 + rsub;
                stg[u] = make_float4(0.f, 0.f, 0.f, 0.f);
                if (node < n_nodes)
                    stg[u] = reinterpret_cast<const float4*>(
                                x + (((size_t)node * M_TOTAL + m) << 7))[fc];
            }
        }

        // ---- mma ks 0..3 ----
        #pragma unroll
        for (int ks = 0; ks < 4; ++ks) {
            const int ach = (2 * ks + a_hi) ^ a_sw;
            uint32_t a[4][4];
            #pragma unroll
            for (int mt = 0; mt < 4; ++mt)
                LDMATRIX_X4(a[mt][0], a[mt][1], a[mt][2], a[mt][3],
                            sA + aoff[mt] + (uint32_t)(ach << 4));
            #pragma unroll
            for (int mt = 0; mt < 4; ++mt) {
                MMA16816(acc[mt][0], a[mt], breg[ks][0], breg[ks][1]);
                MMA16816(acc[mt][1], a[mt], breg[ks][2], breg[ks][3]);
            }
        }

        // ---- convert+store half0, issue LDGs half1 ----
        if (nx) {
            #pragma unroll
            for (int u = 0; u < 4; ++u) {
                __half2 h0 = __floats2half2_rn(stg[u].x, stg[u].y);
                __half2 h1 = __floats2half2_rn(stg[u].z, stg[u].w);
                STS64(sAn + (uint32_t)((u * 16 + rsub) << 8) + swz,
                      *reinterpret_cast<uint32_t*>(&h0),
                      *reinterpret_cast<uint32_t*>(&h1));
            }
            #pragma unroll
            for (int u = 0; u < 4; ++u) {
                int node = nb_next + 64 + u * 16 + rsub;
                stg[u] = make_float4(0.f, 0.f, 0.f, 0.f);
                if (node < n_nodes)
                    stg[u] = reinterpret_cast<const float4*>(
                                x + (((size_t)node * M_TOTAL + m) << 7))[fc];
            }
        }

        // ---- mma ks 4..7 ----
        #pragma unroll
        for (int ks = 4; ks < 8; ++ks) {
            const int ach = (2 * ks + a_hi) ^ a_sw;
            uint32_t a[4][4];
            #pragma unroll
            for (int mt = 0; mt < 4; ++mt)
                LDMATRIX_X4(a[mt][0], a[mt][1], a[mt][2], a[mt][3],
                            sA + aoff[mt] + (uint32_t)(ach << 4));
            #pragma unroll
            for (int mt = 0; mt < 4; ++mt) {
                MMA16816(acc[mt][0], a[mt], breg[ks][0], breg[ks][1]);
                MMA16816(acc[mt][1], a[mt], breg[ks][2], breg[ks][3]);
            }
        }

        // ---- convert+store half1 ----
        if (nx) {
            #pragma unroll
            for (int u = 0; u < 4; ++u) {
                __half2 h0 = __floats2half2_rn(stg[u].x, stg[u].y);
                __half2 h1 = __floats2half2_rn(stg[u].z, stg[u].w);
                STS64(sAn + (uint32_t)((64 + u * 16 + rsub) << 8) + swz,
                      *reinterpret_cast<uint32_t*>(&h0),
                      *reinterpret_cast<uint32_t*>(&h1));
            }
        }

        // ---- epilogue: store tile t ----
        {
            const int node0 = t * TILE_M;
            const int row_in = lane >> 2;
            const int col_in = (lane & 3) << 1;
            #pragma unroll
            for (int mt = 0; mt < 4; ++mt) {
                #pragma unroll
                for (int q2 = 0; q2 < 2; ++q2) {
                    int node = node0 + wr + mt * 16 + q2 * 8 + row_in;
                    if (node < n_nodes) {
                        float* op = out + (((size_t)node * M_TOTAL + m) << 7)
                                  + wc + col_in;
                        #pragma unroll
                        for (int nt = 0; nt < 2; ++nt) {
                            float2 v;
                            v.x = acc[mt][nt][q2 * 2];
                            v.y = acc[mt][nt][q2 * 2 + 1];
                            *reinterpret_cast<float2*>(op + nt * 8) = v;
                        }
                    }
                }
            }
        }
        __syncthreads();
    }
}

// ================= launch =================

extern "C" void kernel_launch(void* const* d_in, const int* in_sizes, int n_in,
                              void* d_out, int out_size) {
    const float* x   = (const float*)d_in[0];
    const float* w   = (const float*)d_in[1];
    const int*   seg = (const int*)d_in[2];
    float* out = (float*)d_out;

    int n_nodes = in_sizes[0] / (M_TOTAL * KDIM);     // 50000
    int ntiles = (n_nodes + TILE_M - 1) / TILE_M;     // 391

    prep_w_kernel<<<(NPATH * NDIM * KDIM) / 256, 256>>>(w);

    static bool attr_set = false;
    if (!attr_set) {
        cudaFuncSetAttribute(irreps_pers_kernel,
                             cudaFuncAttributeMaxDynamicSharedMemorySize, 65536);
        attr_set = true;
    }

    dim3 grid(SLICES, M_TOTAL);   // 9 x 16 = 144 persistent CTAs
    irreps_pers_kernel<<<grid, THREADS, 65536>>>(x, seg, out, n_nodes, ntiles);
}

// round 10
// speedup vs baseline: 1.1839x; 1.0881x over previous
#include <cuda_runtime.h>
#include <cuda_fp16.h>
#include <cstdint>

// ================= config =================
#define THREADS 512
#define SLICES 9          // 9 * 16 = 144 persistent CTAs (one wave, 1 CTA/SM)
#define TILE_M 128
#define KDIM 128
#define NDIM 128
#define M_TOTAL 16
#define NPATH 4

// W converted to fp16, transposed to [p][n][k] (k contiguous) — 128KB, L2-resident.
__device__ __half g_wt[NPATH * NDIM * KDIM];

// ================= helpers =================

__device__ __forceinline__ uint32_t smem_u32(const void* p) {
    uint32_t a;
    asm("{ .reg .u64 t; cvta.to.shared.u64 t, %1; cvt.u32.u64 %0, t; }"
        : "=r"(a) : "l"(p));
    return a;
}

#define LDMATRIX_X4(R0, R1, R2, R3, ADDR)                                  \
    asm volatile("ldmatrix.sync.aligned.m8n8.x4.shared.b16 {%0,%1,%2,%3}, [%4];" \
        : "=r"(R0), "=r"(R1), "=r"(R2), "=r"(R3) : "r"(ADDR))

#define MMA16816(D, A, B0, B1)                                             \
    asm volatile("mma.sync.aligned.m16n8k16.row.col.f32.f16.f16.f32 "      \
        "{%0,%1,%2,%3}, {%4,%5,%6,%7}, {%8,%9}, {%0,%1,%2,%3};"            \
        : "+f"((D)[0]), "+f"((D)[1]), "+f"((D)[2]), "+f"((D)[3])           \
        : "r"((A)[0]), "r"((A)[1]), "r"((A)[2]), "r"((A)[3]),              \
          "r"(B0), "r"(B1))

#define STS64(ADDR, LO, HI)                                                \
    asm volatile("st.shared.v2.b32 [%0], {%1,%2};"                          \
        :: "r"(ADDR), "r"(LO), "r"(HI) : "memory")

#define LDS128(R0, R1, R2, R3, ADDR)                                       \
    asm volatile("ld.shared.v4.b32 {%0,%1,%2,%3}, [%4];"                    \
        : "=r"(R0), "=r"(R1), "=r"(R2), "=r"(R3) : "r"(ADDR))

// cp.async 16B with src-size predication (0 -> zero-fill)
#define CP_ASYNC16(DST, SRC, SZ)                                           \
    asm volatile("cp.async.cg.shared.global [%0], [%1], 16, %2;"            \
        :: "r"(DST), "l"(SRC), "r"(SZ) : "memory")

#define CP_COMMIT() asm volatile("cp.async.commit_group;" ::: "memory")
#define CP_WAIT1()  asm volatile("cp.async.wait_group 1;" ::: "memory")

// ================= prep kernel: W fp32 [p][k][n] -> fp16 [p][n][k] =================

__global__ void prep_w_kernel(const float* __restrict__ w) {
    int idx = blockIdx.x * blockDim.x + threadIdx.x;   // 65536 total
    int p = idx >> 14;
    int n = (idx >> 7) & 127;
    int k = idx & 127;
    g_wt[idx] = __float2half_rn(w[(p << 14) + (k << 7) + n]);
}

// ================= main kernel =================
// 512 threads = 16 warps, warp grid 2(M-groups of 64) x 8(N-groups of 16).
// smem: F0/F1 = 32KB fp16 mma buffers (XOR-swizzled), S0/S1 = 64KB fp32 stage.
// 3-stage pipeline: cp.async(tile i+2) || convert(i+1, S->F) || MMA(i, F).
// B[p] staged once, lives in registers (32/thread).

__global__ void __launch_bounds__(THREADS, 1)
irreps_pers_kernel(const float* __restrict__ x,
                   const int* __restrict__ seg,
                   float* __restrict__ out,
                   int n_nodes, int ntiles) {
    extern __shared__ char smem[];

    const int tid = threadIdx.x;
    const int lane = tid & 31;
    const int wid = tid >> 5;
    const int m = blockIdx.y;
    const int s = blockIdx.x;
    const int p = seg[m];

    const uint32_t sF0 = smem_u32(smem);
    const uint32_t sF1 = sF0 + 32768u;
    const uint32_t sS0 = sF0 + 65536u;
    const uint32_t sS1 = sF0 + 131072u;

    // warp tile: 64 rows x 16 cols
    const int wr = (wid >> 3) * 64;
    const int wc = (wid & 7) * 16;

    const int cnt = (ntiles - s + SLICES - 1) / SLICES;   // >= 43

    // ---- per-thread staging coords: row = u*16 + rsub, 16B col = fc ----
    const int fc = lane;
    const int rsub = wid;
    const uint32_t swz = (uint32_t)((((fc >> 1) ^ (rsub & 7)) << 4) | ((fc & 1) << 3));

    // ---- prologue: start cp.async for tiles 0 and 1 ----
    {
        #pragma unroll
        for (int pi = 0; pi < 2; ++pi) {
            const uint32_t sS = pi ? sS1 : sS0;
            const int nb = (s + pi * SLICES) * TILE_M;
            #pragma unroll
            for (int u = 0; u < 8; ++u) {
                int row = u * 16 + rsub;
                int node = nb + row;
                uint32_t sz = (node < n_nodes) ? 16u : 0u;
                int node_c = (node < n_nodes) ? node : 0;
                const char* src = reinterpret_cast<const char*>(
                    x + (((size_t)node_c * M_TOTAL + m) << 7)) + fc * 16;
                CP_ASYNC16(sS + (uint32_t)(row << 9) + (uint32_t)(fc << 4), src, sz);
            }
            CP_COMMIT();
        }
    }

    // ---- stage B[p] into F1 (swizzled), LDSM to registers ----
    {
        const __half* wt = g_wt + (p << 14);
        #pragma unroll
        for (int i = 0; i < 4; ++i) {
            int cidx = i * THREADS + tid;      // 2048 16B chunks
            int row = cidx >> 4;
            int ch  = cidx & 15;
            uint4 v = *reinterpret_cast<const uint4*>(wt + (row << 7) + (ch << 3));
            uint32_t off = (uint32_t)(row << 8) + (uint32_t)(((ch ^ (row & 7)) << 4));
            *reinterpret_cast<uint4*>(smem + 32768 + off) = v;
        }
    }
    __syncthreads();

    const int b_row = wc + (lane & 7) + ((lane >> 4) << 3);
    const uint32_t b_base = sF1 + (uint32_t)(b_row << 8);
    const int b_sw = b_row & 7;
    const int b_hi = (lane >> 3) & 1;

    uint32_t breg[8][4];
    #pragma unroll
    for (int ks = 0; ks < 8; ++ks) {
        const int bch = (2 * ks + b_hi) ^ b_sw;
        LDMATRIX_X4(breg[ks][0], breg[ks][1], breg[ks][2], breg[ks][3],
                    b_base + (uint32_t)(bch << 4));
    }
    __syncthreads();   // B reads done before F1 reused

    // ---- A fragment addressing ----
    const int a_hi = lane >> 4;
    const int a_sw = lane & 7;
    uint32_t aoff[4];
    #pragma unroll
    for (int mt = 0; mt < 4; ++mt)
        aoff[mt] = (uint32_t)((wr + mt * 16 + (lane & 15)) << 8);

    // ---- prologue: convert tile 0 (S0 -> F0) ----
    CP_WAIT1();
    #pragma unroll
    for (int u = 0; u < 8; ++u) {
        int row = u * 16 + rsub;
        uint32_t r0, r1, r2, r3;
        LDS128(r0, r1, r2, r3, sS0 + (uint32_t)(row << 9) + (uint32_t)(fc << 4));
        __half2 h0 = __floats2half2_rn(__uint_as_float(r0), __uint_as_float(r1));
        __half2 h1 = __floats2half2_rn(__uint_as_float(r2), __uint_as_float(r3));
        STS64(sF0 + (uint32_t)(row << 8) + swz,
              *reinterpret_cast<uint32_t*>(&h0),
              *reinterpret_cast<uint32_t*>(&h1));
    }
    __syncthreads();

    // ================= main loop =================
    for (int i = 0; i < cnt; ++i) {
        const int j = i & 1;
        const int t = s + i * SLICES;
        const uint32_t sF = j ? sF1 : sF0;

        // ---- issue cp.async for tile i+2 into S(i&1) ----
        if (i + 2 < cnt) {
            const uint32_t sS = j ? sS1 : sS0;
            const int nb = (s + (i + 2) * SLICES) * TILE_M;
            #pragma unroll
            for (int u = 0; u < 8; ++u) {
                int row = u * 16 + rsub;
                int node = nb + row;
                uint32_t sz = (node < n_nodes) ? 16u : 0u;
                int node_c = (node < n_nodes) ? node : 0;
                const char* src = reinterpret_cast<const char*>(
                    x + (((size_t)node_c * M_TOTAL + m) << 7)) + fc * 16;
                CP_ASYNC16(sS + (uint32_t)(row << 9) + (uint32_t)(fc << 4), src, sz);
            }
        }
        CP_COMMIT();   // always commit so wait_group counts stay aligned
        CP_WAIT1();    // tile i+1 resident in S((i+1)&1)

        // ---- convert tile i+1: S((i+1)&1) -> F((i+1)&1) ----
        if (i + 1 < cnt) {
            const uint32_t sSn = j ? sS0 : sS1;
            const uint32_t sFn = j ? sF0 : sF1;
            #pragma unroll
            for (int u = 0; u < 8; ++u) {
                int row = u * 16 + rsub;
                uint32_t r0, r1, r2, r3;
                LDS128(r0, r1, r2, r3, sSn + (uint32_t)(row << 9) + (uint32_t)(fc << 4));
                __half2 h0 = __floats2half2_rn(__uint_as_float(r0), __uint_as_float(r1));
                __half2 h1 = __floats2half2_rn(__uint_as_float(r2), __uint_as_float(r3));
                STS64(sFn + (uint32_t)(row << 8) + swz,
                      *reinterpret_cast<uint32_t*>(&h0),
                      *reinterpret_cast<uint32_t*>(&h1));
            }
        }

        // ---- MMA on tile i from F(i&1) ----
        float acc[4][2][4];
        #pragma unroll
        for (int mt = 0; mt < 4; ++mt)
            #pragma unroll
            for (int nt = 0; nt < 2; ++nt)
                #pragma unroll
                for (int q = 0; q < 4; ++q)
                    acc[mt][nt][q] = 0.0f;

        #pragma unroll
        for (int ks = 0; ks < 8; ++ks) {
            const int ach = (2 * ks + a_hi) ^ a_sw;
            uint32_t a[4][4];
            #pragma unroll
            for (int mt = 0; mt < 4; ++mt)
                LDMATRIX_X4(a[mt][0], a[mt][1], a[mt][2], a[mt][3],
                            sF + aoff[mt] + (uint32_t)(ach << 4));
            #pragma unroll
            for (int mt = 0; mt < 4; ++mt) {
                MMA16816(acc[mt][0], a[mt], breg[ks][0], breg[ks][1]);
                MMA16816(acc[mt][1], a[mt], breg[ks][2], breg[ks][3]);
            }
        }

        // ---- epilogue: store tile i ----
        {
            const int node0 = t * TILE_M;
            const int row_in = lane >> 2;
            const int col_in = (lane & 3) << 1;
            #pragma unroll
            for (int mt = 0; mt < 4; ++mt) {
                #pragma unroll
                for (int q2 = 0; q2 < 2; ++q2) {
                    int node = node0 + wr + mt * 16 + q2 * 8 + row_in;
                    if (node < n_nodes) {
                        float* op = out + (((size_t)node * M_TOTAL + m) << 7)
                                  + wc + col_in;
                        #pragma unroll
                        for (int nt = 0; nt < 2; ++nt) {
                            float2 v;
                            v.x = acc[mt][nt][q2 * 2];
                            v.y = acc[mt][nt][q2 * 2 + 1];
                            *reinterpret_cast<float2*>(op + nt * 8) = v;
                        }
                    }
                }
            }
        }
        __syncthreads();
    }
}

// ================= launch =================

extern "C" void kernel_launch(void* const* d_in, const int* in_sizes, int n_in,
                              void* d_out, int out_size) {
    const float* x   = (const float*)d_in[0];
    const float* w   = (const float*)d_in[1];
    const int*   seg = (const int*)d_in[2];
    float* out = (float*)d_out;

    int n_nodes = in_sizes[0] / (M_TOTAL * KDIM);     // 50000
    int ntiles = (n_nodes + TILE_M - 1) / TILE_M;     // 391

    prep_w_kernel<<<(NPATH * NDIM * KDIM) / 256, 256>>>(w);

    static bool attr_set = false;
    if (!attr_set) {
        cudaFuncSetAttribute(irreps_pers_kernel,
                             cudaFuncAttributeMaxDynamicSharedMemorySize, 196608);
        attr_set = true;
    }

    dim3 grid(SLICES, M_TOTAL);   // 9 x 16 = 144 persistent CTAs
    irreps_pers_kernel<<<grid, THREADS, 196608>>>(x, seg, out, n_nodes, ntiles);
}